// round 1
// baseline (speedup 1.0000x reference)
#include <cuda_runtime.h>
#include <cuda_bf16.h>

// Problem constants
#define BB 4
#define CC 256
#define HH 256
#define WW 256
#define RR 64
#define HL 64
#define WL 64
#define PL (HL*WL)          // 4096 low-res pixels

// Scratch (no cudaMalloc allowed -> __device__ globals)
__device__ float g_Elr[BB*CC*PL];   // 16 MB  downsampled F_enc
__device__ float g_Dlr[BB*CC*PL];   // 16 MB  downsampled F_dec
__device__ float g_fg [BB*RR*PL];   // 4 MB
__device__ float g_ft [BB*RR*PL];   // 4 MB
__device__ float g_a  [BB*RR*PL];   // 4 MB
__device__ float g_b  [BB*RR*PL];   // 4 MB
__device__ float g_Ai [BB*CC*PL];   // 16 MB  a expanded to C channels (low res)
__device__ float g_Bi [BB*CC*PL];   // 16 MB  b expanded to C channels (low res)

// ---------- packed f32x2 helpers ----------
__device__ __forceinline__ unsigned long long pk2(float lo, float hi) {
    unsigned long long r;
    asm("mov.b64 %0, {%1, %2};" : "=l"(r) : "f"(lo), "f"(hi));
    return r;
}
__device__ __forceinline__ void fma2(unsigned long long& acc, unsigned long long a,
                                     unsigned long long b) {
    asm("fma.rn.f32x2 %0, %1, %2, %0;" : "+l"(acc) : "l"(a), "l"(b));
}
__device__ __forceinline__ float unpk_sum(unsigned long long v) {
    float lo, hi;
    asm("mov.b64 {%0, %1}, %2;" : "=f"(lo), "=f"(hi) : "l"(v));
    return lo + hi;
}

// ---------- K1: 4x bilinear downsample of both full-res inputs ----------
// With in=256, out=64, align_corners=False: src = 4*i + 1.5 -> avg of rows/cols {4i+1,4i+2}.
__global__ __launch_bounds__(256) void k_down(const float* __restrict__ E,
                                              const float* __restrict__ D) {
    int idx = blockIdx.x * blockDim.x + threadIdx.x;     // [0, B*C*PL)
    int j  = idx & 63;
    int i  = (idx >> 6) & 63;
    int bc = idx >> 12;
    const float* eb = E + (size_t)bc * (HH*WW);
    const float* db = D + (size_t)bc * (HH*WW);
    int o = (4*i + 1) * WW + (4*j + 1);
    float e = 0.25f * (eb[o] + eb[o+1] + eb[o+WW] + eb[o+WW+1]);
    float d = 0.25f * (db[o] + db[o+1] + db[o+WW] + db[o+WW+1]);
    g_Elr[idx] = e;
    g_Dlr[idx] = d;
}

// ---------- K2: low-res 1x1 projection: out[b,r,p] = sum_c w[r,c] * in[b,c,p] ----------
// which: 0 -> (g_Elr -> g_fg), 1 -> (g_Dlr -> g_ft). 32 r-rows per block (blockIdx.z).
// Packed over channel pairs: acc[r] holds (even-c partial, odd-c partial).
__global__ __launch_bounds__(128) void k_proj(const float* __restrict__ w, int which) {
    __shared__ float ws[32 * CC];
    const float* in = which ? g_Dlr : g_Elr;
    float* out      = which ? g_ft  : g_fg;
    int b  = blockIdx.x;          // 0..3
    int pt = blockIdx.y;          // 0..31 (pixel tiles of 128)
    int rh = blockIdx.z;          // 0..1
    int tid = threadIdx.x;

    const float4* wsrc = (const float4*)(w + rh * 32 * CC);
    float4* wdst = (float4*)ws;
    #pragma unroll
    for (int i = tid; i < 32 * CC / 4; i += 128) wdst[i] = wsrc[i];
    __syncthreads();

    int p = pt * 128 + tid;
    const float* inb = in + (size_t)b * CC * PL + p;

    unsigned long long acc[32];
    #pragma unroll
    for (int r = 0; r < 32; r++) acc[r] = 0ull;

    for (int c = 0; c < CC; c += 4) {
        float e0 = inb[(size_t)(c+0) * PL];
        float e1 = inb[(size_t)(c+1) * PL];
        float e2 = inb[(size_t)(c+2) * PL];
        float e3 = inb[(size_t)(c+3) * PL];
        unsigned long long ep0 = pk2(e0, e1);
        unsigned long long ep1 = pk2(e2, e3);
        #pragma unroll
        for (int r = 0; r < 32; r++) {
            // warp-uniform SMEM address -> broadcast LDS.128
            const ulonglong2 wv = *(const ulonglong2*)(ws + r * CC + c);
            fma2(acc[r], ep0, wv.x);
            fma2(acc[r], ep1, wv.y);
        }
    }
    float* outp = out + ((size_t)b * RR + rh * 32) * PL + p;
    #pragma unroll
    for (int r = 0; r < 32; r++) outp[(size_t)r * PL] = unpk_sum(acc[r]);
}

// ---------- K3: 3x3 zero-padded box stats + guided-filter coefficients ----------
__global__ __launch_bounds__(256) void k_guided(const float* __restrict__ epsPtr) {
    __shared__ float sg[PL];
    __shared__ float st[PL];
    int br = blockIdx.x;                       // b*RR + r, 256 blocks
    int tid = threadIdx.x;
    const float* gsrc = g_fg + (size_t)br * PL;
    const float* tsrc = g_ft + (size_t)br * PL;
    #pragma unroll
    for (int i = tid; i < PL/4; i += 256) {
        ((float4*)sg)[i] = ((const float4*)gsrc)[i];
        ((float4*)st)[i] = ((const float4*)tsrc)[i];
    }
    __syncthreads();
    float eps = *epsPtr;
    const float inv9 = 1.0f / 9.0f;
    for (int p = tid; p < PL; p += 256) {
        int i = p >> 6, j = p & 63;
        float sgs = 0.f, sts = 0.f, sggs = 0.f, sgts = 0.f;
        #pragma unroll
        for (int di = -1; di <= 1; di++) {
            int ii = i + di;
            if (ii < 0 || ii > 63) continue;
            #pragma unroll
            for (int dj = -1; dj <= 1; dj++) {
                int jj = j + dj;
                if (jj < 0 || jj > 63) continue;
                float g = sg[ii*64 + jj];
                float t = st[ii*64 + jj];
                sgs += g; sts += t; sggs += g*g; sgts += g*t;
            }
        }
        float mg  = sgs * inv9;
        float mt  = sts * inv9;
        float var = sggs * inv9 - mg * mg;
        float cov = sgts * inv9 - mg * mt;
        float a   = cov / (var + eps);
        float bb  = mt - a * mg;
        g_a[(size_t)br * PL + p] = a;
        g_b[(size_t)br * PL + p] = bb;
    }
}

// ---------- K4: expand: out[b,o,p] = sum_r w[o,r] * in[b,r,p]  (w: [C, R]) ----------
// which: 0 -> (g_a -> g_Ai), 1 -> (g_b -> g_Bi). 32 o-rows per block (blockIdx.z of 8).
__global__ __launch_bounds__(128) void k_expand(const float* __restrict__ w, int which) {
    __shared__ float ws[32 * RR];
    const float* in = which ? g_b  : g_a;
    float* out      = which ? g_Bi : g_Ai;
    int b  = blockIdx.x;          // 0..3
    int pt = blockIdx.y;          // 0..31
    int oh = blockIdx.z;          // 0..7
    int tid = threadIdx.x;

    const float4* wsrc = (const float4*)(w + oh * 32 * RR);
    #pragma unroll
    for (int i = tid; i < 32 * RR / 4; i += 128) ((float4*)ws)[i] = wsrc[i];
    __syncthreads();

    int p = pt * 128 + tid;
    const float* inb = in + (size_t)b * RR * PL + p;

    unsigned long long acc[32];
    #pragma unroll
    for (int o = 0; o < 32; o++) acc[o] = 0ull;

    for (int r = 0; r < RR; r += 4) {
        float e0 = inb[(size_t)(r+0) * PL];
        float e1 = inb[(size_t)(r+1) * PL];
        float e2 = inb[(size_t)(r+2) * PL];
        float e3 = inb[(size_t)(r+3) * PL];
        unsigned long long ep0 = pk2(e0, e1);
        unsigned long long ep1 = pk2(e2, e3);
        #pragma unroll
        for (int o = 0; o < 32; o++) {
            const ulonglong2 wv = *(const ulonglong2*)(ws + o * RR + r);
            fma2(acc[o], ep0, wv.x);
            fma2(acc[o], ep1, wv.y);
        }
    }
    float* outp = out + ((size_t)b * CC + oh * 32) * PL + p;
    #pragma unroll
    for (int o = 0; o < 32; o++) outp[(size_t)o * PL] = unpk_sum(acc[o]);
}

// ---------- K5: fused 4x bilinear upsample + output combine ----------
// Each thread owns one x-group of 4 output pixels (x = 4k..4k+3) for one (b,c,y).
// Low-res columns needed: {k-1, k, k+1} (clamped), rows {y0, y1}.
// Interior x-weights are the fixed pattern {0.625, 0.875, 0.125, 0.375};
// at k==0 the first two become 0 (src clamped to 0).
__global__ __launch_bounds__(256) void k_final(const float* __restrict__ E,
                                               const float* __restrict__ D,
                                               float* __restrict__ out) {
    int idx = blockIdx.x * blockDim.x + threadIdx.x;   // [0, B*C*H*(W/4))
    int k  = idx & 63;
    int y  = (idx >> 6) & 255;
    int bc = idx >> 14;

    // y interpolation (align_corners=False, scale=0.25)
    float sy = fmaxf((y + 0.5f) * 0.25f - 0.5f, 0.0f);
    int y0 = (int)sy; if (y0 > 63) y0 = 63;
    int y1 = min(y0 + 1, 63);
    float wy = sy - (float)y0;
    float cwy = 1.0f - wy;

    const float* Ab = g_Ai + (size_t)bc * PL;
    const float* Bb = g_Bi + (size_t)bc * PL;
    int cl = max(k - 1, 0);
    int cr = min(k + 1, 63);

    const float* A0 = Ab + y0 * 64;
    const float* A1 = Ab + y1 * 64;
    const float* B0 = Bb + y0 * 64;
    const float* B1 = Bb + y1 * 64;

    float al = A0[cl]*cwy + A1[cl]*wy;
    float am = A0[k ]*cwy + A1[k ]*wy;
    float ar = A0[cr]*cwy + A1[cr]*wy;
    float bl = B0[cl]*cwy + B1[cl]*wy;
    float bm = B0[k ]*cwy + B1[k ]*wy;
    float br = B0[cr]*cwy + B1[cr]*wy;

    float w0 = (k == 0) ? 0.0f : 0.625f;
    float w1 = (k == 0) ? 0.0f : 0.875f;
    const float w2 = 0.125f, w3 = 0.375f;

    float a0 = al*(1.0f - w0) + am*w0;
    float a1 = al*(1.0f - w1) + am*w1;
    float a2 = am*(1.0f - w2) + ar*w2;
    float a3 = am*(1.0f - w3) + ar*w3;
    float b0 = bl*(1.0f - w0) + bm*w0;
    float b1 = bl*(1.0f - w1) + bm*w1;
    float b2 = bm*(1.0f - w2) + br*w2;
    float b3 = bm*(1.0f - w3) + br*w3;

    size_t base = (size_t)idx * 4;    // == ((bc*256 + y)*256 + 4k)
    float4 e = *(const float4*)(E + base);
    float4 d = *(const float4*)(D + base);
    float4 o;
    o.x = d.x + a0 * e.x + b0;
    o.y = d.y + a1 * e.y + b1;
    o.z = d.z + a2 * e.z + b2;
    o.w = d.w + a3 * e.w + b3;
    *(float4*)(out + base) = o;
}

extern "C" void kernel_launch(void* const* d_in, const int* in_sizes, int n_in,
                              void* d_out, int out_size) {
    const float* F_enc = (const float*)d_in[0];
    const float* F_dec = (const float*)d_in[1];
    const float* w_rg  = (const float*)d_in[2];
    const float* w_rt  = (const float*)d_in[3];
    const float* w_ua  = (const float*)d_in[4];
    const float* w_ub  = (const float*)d_in[5];
    const float* eps   = (const float*)d_in[6];
    float* out = (float*)d_out;

    // K1: downsample both inputs 4x
    k_down<<<(BB*CC*PL)/256, 256>>>(F_enc, F_dec);

    // K2: low-res projections to R channels
    {
        dim3 g(BB, PL/128, 2);
        k_proj<<<g, 128>>>(w_rg, 0);
        k_proj<<<g, 128>>>(w_rt, 1);
    }

    // K3: box stats + a,b
    k_guided<<<BB*RR, 256>>>(eps);

    // K4: expand a,b to C channels at low res
    {
        dim3 g(BB, PL/128, 8);
        k_expand<<<g, 128>>>(w_ua, 0);
        k_expand<<<g, 128>>>(w_ub, 1);
    }

    // K5: fused upsample + combine
    k_final<<<(BB*CC*HH*(WW/4))/256, 256>>>(F_enc, F_dec, out);
}

// round 2
// speedup vs baseline: 1.4013x; 1.4013x over previous
#include <cuda_runtime.h>
#include <cuda_bf16.h>

// Problem constants
#define BB 4
#define CC 256
#define HH 256
#define WW 256
#define RR 64
#define HL 64
#define WL 64
#define PL (HL*WL)          // 4096 low-res pixels

// Scratch (no cudaMalloc allowed -> __device__ globals)
__device__ float g_Elr[BB*CC*PL];   // 16 MB  downsampled F_enc
__device__ float g_Dlr[BB*CC*PL];   // 16 MB  downsampled F_dec
__device__ float g_fg [BB*RR*PL];   // 4 MB
__device__ float g_ft [BB*RR*PL];   // 4 MB
__device__ float g_a  [BB*RR*PL];   // 4 MB
__device__ float g_b  [BB*RR*PL];   // 4 MB
__device__ float g_Ai [BB*CC*PL];   // 16 MB  a expanded to C channels (low res)
__device__ float g_Bi [BB*CC*PL];   // 16 MB  b expanded to C channels (low res)

// ---------- packed f32x2 helpers ----------
__device__ __forceinline__ unsigned long long pk2(float lo, float hi) {
    unsigned long long r;
    asm("mov.b64 %0, {%1, %2};" : "=l"(r) : "f"(lo), "f"(hi));
    return r;
}
__device__ __forceinline__ void fma2(unsigned long long& acc, unsigned long long a,
                                     unsigned long long b) {
    asm("fma.rn.f32x2 %0, %1, %2, %0;" : "+l"(acc) : "l"(a), "l"(b));
}
__device__ __forceinline__ float unpk_sum(unsigned long long v) {
    float lo, hi;
    asm("mov.b64 {%0, %1}, %2;" : "=f"(lo), "=f"(hi) : "l"(v));
    return lo + hi;
}

// ---------- K1: 4x bilinear downsample of both full-res inputs ----------
// With in=256, out=64, align_corners=False: src = 4*i + 1.5 -> avg of rows/cols
// {4i+1,4i+2}. Cols 4j+1,4j+2 live inside the aligned float4 at col 4j, so each
// thread does 4 fully-coalesced LDG.128 (2 rows x 2 tensors) and uses .y/.z.
__global__ __launch_bounds__(256) void k_down(const float* __restrict__ E,
                                              const float* __restrict__ D) {
    int idx = blockIdx.x * blockDim.x + threadIdx.x;     // [0, B*C*PL)
    int j  = idx & 63;
    int i  = (idx >> 6) & 63;
    int bc = idx >> 12;
    const float4* eb = (const float4*)(E + (size_t)bc * (HH*WW));
    const float4* db = (const float4*)(D + (size_t)bc * (HH*WW));
    int r0 = (4*i + 1) * (WW/4) + j;       // float4 index of row 4i+1, col-group j
    float4 e0 = eb[r0];
    float4 e1 = eb[r0 + WW/4];
    float4 d0 = db[r0];
    float4 d1 = db[r0 + WW/4];
    g_Elr[idx] = 0.25f * (e0.y + e0.z + e1.y + e1.z);
    g_Dlr[idx] = 0.25f * (d0.y + d0.z + d1.y + d1.z);
}

// ---------- K2: low-res 1x1 projection: out[b,r,p] = sum_c w[r,c] * in[b,c,p] ----------
// blockIdx.z: bit0 = r-half, bit1 = which tensor (0: Elr->fg w_rg, 1: Dlr->ft w_rt)
__global__ __launch_bounds__(128) void k_proj(const float* __restrict__ wg,
                                              const float* __restrict__ wt) {
    __shared__ float ws[32 * CC];
    int which = blockIdx.z >> 1;
    int rh    = blockIdx.z & 1;
    const float* in = which ? g_Dlr : g_Elr;
    float* out      = which ? g_ft  : g_fg;
    const float* w  = which ? wt    : wg;
    int b  = blockIdx.x;          // 0..3
    int pt = blockIdx.y;          // 0..31 (pixel tiles of 128)
    int tid = threadIdx.x;

    const float4* wsrc = (const float4*)(w + rh * 32 * CC);
    float4* wdst = (float4*)ws;
    #pragma unroll
    for (int i = tid; i < 32 * CC / 4; i += 128) wdst[i] = wsrc[i];
    __syncthreads();

    int p = pt * 128 + tid;
    const float* inb = in + (size_t)b * CC * PL + p;

    unsigned long long acc[32];
    #pragma unroll
    for (int r = 0; r < 32; r++) acc[r] = 0ull;

    for (int c = 0; c < CC; c += 4) {
        float e0 = inb[(size_t)(c+0) * PL];
        float e1 = inb[(size_t)(c+1) * PL];
        float e2 = inb[(size_t)(c+2) * PL];
        float e3 = inb[(size_t)(c+3) * PL];
        unsigned long long ep0 = pk2(e0, e1);
        unsigned long long ep1 = pk2(e2, e3);
        #pragma unroll
        for (int r = 0; r < 32; r++) {
            const ulonglong2 wv = *(const ulonglong2*)(ws + r * CC + c);
            fma2(acc[r], ep0, wv.x);
            fma2(acc[r], ep1, wv.y);
        }
    }
    float* outp = out + ((size_t)b * RR + rh * 32) * PL + p;
    #pragma unroll
    for (int r = 0; r < 32; r++) outp[(size_t)r * PL] = unpk_sum(acc[r]);
}

// ---------- K3: 3x3 zero-padded box stats + guided-filter coefficients ----------
// 66x66 zero-padded SMEM tiles -> branch-free 9-tap accumulation.
#define PITCH 66
__global__ __launch_bounds__(256) void k_guided(const float* __restrict__ epsPtr) {
    __shared__ float sg[PITCH*PITCH];
    __shared__ float st[PITCH*PITCH];
    int br = blockIdx.x;                       // b*RR + r, 256 blocks
    int tid = threadIdx.x;
    const float* gsrc = g_fg + (size_t)br * PL;
    const float* tsrc = g_ft + (size_t)br * PL;
    // zero borders (fill everything, cheap)
    for (int i = tid; i < PITCH*PITCH; i += 256) { sg[i] = 0.0f; st[i] = 0.0f; }
    __syncthreads();
    for (int p = tid; p < PL; p += 256) {
        int i = p >> 6, j = p & 63;
        sg[(i+1)*PITCH + (j+1)] = gsrc[p];
        st[(i+1)*PITCH + (j+1)] = tsrc[p];
    }
    __syncthreads();
    float eps = *epsPtr;
    const float inv9 = 1.0f / 9.0f;
    for (int p = tid; p < PL; p += 256) {
        int i = p >> 6, j = p & 63;
        int c = (i+1)*PITCH + (j+1);
        float sgs = 0.f, sts = 0.f, sggs = 0.f, sgts = 0.f;
        #pragma unroll
        for (int di = -1; di <= 1; di++) {
            #pragma unroll
            for (int dj = -1; dj <= 1; dj++) {
                float g = sg[c + di*PITCH + dj];
                float t = st[c + di*PITCH + dj];
                sgs += g; sts += t; sggs += g*g; sgts += g*t;
            }
        }
        float mg  = sgs * inv9;
        float mt  = sts * inv9;
        float var = sggs * inv9 - mg * mg;
        float cov = sgts * inv9 - mg * mt;
        float a   = cov / (var + eps);
        float bb  = mt - a * mg;
        g_a[(size_t)br * PL + p] = a;
        g_b[(size_t)br * PL + p] = bb;
    }
}

// ---------- K4: expand: out[b,o,p] = sum_r w[o,r] * in[b,r,p]  (w: [C, R]) ----------
// blockIdx.z: bits [0:3) = o-chunk (8), bit3 = which (0: a->Ai w_ua, 1: b->Bi w_ub)
__global__ __launch_bounds__(128) void k_expand(const float* __restrict__ wa,
                                                const float* __restrict__ wb) {
    __shared__ float ws[32 * RR];
    int which = blockIdx.z >> 3;
    int oh    = blockIdx.z & 7;
    const float* in = which ? g_b  : g_a;
    float* out      = which ? g_Bi : g_Ai;
    const float* w  = which ? wb   : wa;
    int b  = blockIdx.x;          // 0..3
    int pt = blockIdx.y;          // 0..31
    int tid = threadIdx.x;

    const float4* wsrc = (const float4*)(w + oh * 32 * RR);
    #pragma unroll
    for (int i = tid; i < 32 * RR / 4; i += 128) ((float4*)ws)[i] = wsrc[i];
    __syncthreads();

    int p = pt * 128 + tid;
    const float* inb = in + (size_t)b * RR * PL + p;

    unsigned long long acc[32];
    #pragma unroll
    for (int o = 0; o < 32; o++) acc[o] = 0ull;

    for (int r = 0; r < RR; r += 4) {
        float e0 = inb[(size_t)(r+0) * PL];
        float e1 = inb[(size_t)(r+1) * PL];
        float e2 = inb[(size_t)(r+2) * PL];
        float e3 = inb[(size_t)(r+3) * PL];
        unsigned long long ep0 = pk2(e0, e1);
        unsigned long long ep1 = pk2(e2, e3);
        #pragma unroll
        for (int o = 0; o < 32; o++) {
            const ulonglong2 wv = *(const ulonglong2*)(ws + o * RR + r);
            fma2(acc[o], ep0, wv.x);
            fma2(acc[o], ep1, wv.y);
        }
    }
    float* outp = out + ((size_t)b * CC + oh * 32) * PL + p;
    #pragma unroll
    for (int o = 0; o < 32; o++) outp[(size_t)o * PL] = unpk_sum(acc[o]);
}

// ---------- K5: fused 4x bilinear upsample + output combine (SMEM-staged) ----------
// Block = (bc plane, tile of 16 output rows). Stage the 6 needed low-res rows of
// Ai/Bi in SMEM, precompute row-interpolated Ay/By[16][64], then pure float4
// streaming of E/D/out with 6 LDS per 4 output pixels.
__global__ __launch_bounds__(256) void k_final(const float* __restrict__ E,
                                               const float* __restrict__ D,
                                               float* __restrict__ out) {
    __shared__ float rawA[6][64], rawB[6][64];
    __shared__ float Ay[16][64], By[16][64];
    int bc = blockIdx.x;      // 0..1023
    int t  = blockIdx.y;      // 0..15 (y tiles of 16)
    int tid = threadIdx.x;
    int base = 4*t - 1;

    const float* Ab = g_Ai + (size_t)bc * PL;
    const float* Bb = g_Bi + (size_t)bc * PL;
    for (int i = tid; i < 6*64; i += 256) {
        int s = i >> 6, c = i & 63;
        int row = min(max(base + s, 0), 63);
        rawA[s][c] = Ab[row*64 + c];
        rawB[s][c] = Bb[row*64 + c];
    }
    __syncthreads();

    for (int i = tid; i < 16*64; i += 256) {
        int yl = i >> 6, c = i & 63;
        int y = t*16 + yl;
        float sy = fmaxf((y + 0.5f) * 0.25f - 0.5f, 0.0f);
        int y0 = (int)sy; if (y0 > 63) y0 = 63;
        int y1 = min(y0 + 1, 63);
        float wy = sy - (float)y0;
        int s0 = y0 - base, s1 = y1 - base;
        float a0 = rawA[s0][c], a1 = rawA[s1][c];
        float b0 = rawB[s0][c], b1 = rawB[s1][c];
        Ay[yl][c] = a0 + wy * (a1 - a0);
        By[yl][c] = b0 + wy * (b1 - b0);
    }
    __syncthreads();

    int yl = tid >> 4;        // 0..15
    int kq = tid & 15;        // 0..15
    int y  = t*16 + yl;
    size_t rowbase = ((size_t)bc * HH + y) * WW;

    #pragma unroll
    for (int g = 0; g < 4; g++) {
        int k = g*16 + kq;
        int cl = max(k - 1, 0);
        int cr = min(k + 1, 63);
        float al = Ay[yl][cl], am = Ay[yl][k], ar = Ay[yl][cr];
        float bl = By[yl][cl], bm = By[yl][k], br = By[yl][cr];

        float w0 = (k == 0) ? 0.0f : 0.625f;
        float w1 = (k == 0) ? 0.0f : 0.875f;
        float a0 = al + w0 * (am - al);
        float a1 = al + w1 * (am - al);
        float a2 = am + 0.125f * (ar - am);
        float a3 = am + 0.375f * (ar - am);
        float b0 = bl + w0 * (bm - bl);
        float b1 = bl + w1 * (bm - bl);
        float b2 = bm + 0.125f * (br - bm);
        float b3 = bm + 0.375f * (br - bm);

        size_t o4 = rowbase + 4*k;
        float4 e = *(const float4*)(E + o4);
        float4 d = *(const float4*)(D + o4);
        float4 o;
        o.x = d.x + a0 * e.x + b0;
        o.y = d.y + a1 * e.y + b1;
        o.z = d.z + a2 * e.z + b2;
        o.w = d.w + a3 * e.w + b3;
        *(float4*)(out + o4) = o;
    }
}

extern "C" void kernel_launch(void* const* d_in, const int* in_sizes, int n_in,
                              void* d_out, int out_size) {
    const float* F_enc = (const float*)d_in[0];
    const float* F_dec = (const float*)d_in[1];
    const float* w_rg  = (const float*)d_in[2];
    const float* w_rt  = (const float*)d_in[3];
    const float* w_ua  = (const float*)d_in[4];
    const float* w_ub  = (const float*)d_in[5];
    const float* eps   = (const float*)d_in[6];
    float* out = (float*)d_out;

    // K1: downsample both inputs 4x (coalesced float4 reads)
    k_down<<<(BB*CC*PL)/256, 256>>>(F_enc, F_dec);

    // K2: low-res projections to R channels (both tensors in one launch)
    k_proj<<<dim3(BB, PL/128, 4), 128>>>(w_rg, w_rt);

    // K3: box stats + a,b (branch-free padded tile)
    k_guided<<<BB*RR, 256>>>(eps);

    // K4: expand a,b to C channels at low res (both in one launch)
    k_expand<<<dim3(BB, PL/128, 16), 128>>>(w_ua, w_ub);

    // K5: fused upsample + combine (SMEM-staged coefficients)
    k_final<<<dim3(BB*CC, HH/16), 256>>>(F_enc, F_dec, out);
}

// round 4
// speedup vs baseline: 1.4124x; 1.0079x over previous
#include <cuda_runtime.h>
#include <cuda_bf16.h>

// Problem constants
#define BB 4
#define CC 256
#define HH 256
#define WW 256
#define RR 64
#define HL 64
#define WL 64
#define PL (HL*WL)          // 4096 low-res pixels

// Scratch (no cudaMalloc allowed -> __device__ globals)
__device__ float g_Elr[BB*CC*PL];   // 16 MB  downsampled F_enc
__device__ float g_Dlr[BB*CC*PL];   // 16 MB  downsampled F_dec
__device__ float g_fg [BB*RR*PL];   // 4 MB
__device__ float g_ft [BB*RR*PL];   // 4 MB
__device__ float g_a  [BB*RR*PL];   // 4 MB
__device__ float g_b  [BB*RR*PL];   // 4 MB
__device__ float g_Ai [BB*CC*PL];   // 16 MB  a expanded to C channels (low res)
__device__ float g_Bi [BB*CC*PL];   // 16 MB  b expanded to C channels (low res)

// ---------- packed f32x2 helpers ----------
__device__ __forceinline__ unsigned long long pk2(float lo, float hi) {
    unsigned long long r;
    asm("mov.b64 %0, {%1, %2};" : "=l"(r) : "f"(lo), "f"(hi));
    return r;
}
__device__ __forceinline__ void fma2(unsigned long long& acc, unsigned long long a,
                                     unsigned long long b) {
    asm("fma.rn.f32x2 %0, %1, %2, %0;" : "+l"(acc) : "l"(a), "l"(b));
}
__device__ __forceinline__ float unpk_sum(unsigned long long v) {
    float lo, hi;
    asm("mov.b64 {%0, %1}, %2;" : "=f"(lo), "=f"(hi) : "l"(v));
    return lo + hi;
}

// ---------- K1: 4x bilinear downsample of both full-res inputs ----------
// out=64 from in=256 (align_corners=False): src = 4*i + 1.5 -> average of rows/cols
// {4i+1, 4i+2}. Cols 4j+1,4j+2 sit inside the aligned float4 at col 4j, so each
// thread does 4 fully-coalesced LDG.128 (2 rows x 2 tensors) and uses .y/.z.
__global__ __launch_bounds__(256) void k_down(const float* __restrict__ E,
                                              const float* __restrict__ D) {
    int idx = blockIdx.x * blockDim.x + threadIdx.x;     // [0, B*C*PL)
    int j  = idx & 63;
    int i  = (idx >> 6) & 63;
    int bc = idx >> 12;
    const float4* eb = (const float4*)(E + (size_t)bc * (HH*WW));
    const float4* db = (const float4*)(D + (size_t)bc * (HH*WW));
    int r0 = (4*i + 1) * (WW/4) + j;       // float4 index of row 4i+1, col-group j
    float4 e0 = eb[r0];
    float4 e1 = eb[r0 + WW/4];
    float4 d0 = db[r0];
    float4 d1 = db[r0 + WW/4];
    g_Elr[idx] = 0.25f * (e0.y + e0.z + e1.y + e1.z);
    g_Dlr[idx] = 0.25f * (d0.y + d0.z + d1.y + d1.z);
}

// ---------- K2: low-res 1x1 projection: out[b,r,p] = sum_c w[r,c] * in[b,c,p] ----------
// Register-tiled: each thread computes 16 r-outputs for 2 pixels.
// blockIdx.z (8): bits[0:2) = r-quarter, bit2 = which tensor.
__global__ __launch_bounds__(128, 5) void k_proj(const float* __restrict__ wg,
                                                 const float* __restrict__ wt) {
    __shared__ float ws[16 * CC];
    int which = blockIdx.z >> 2;
    int rq    = blockIdx.z & 3;
    const float* in = which ? g_Dlr : g_Elr;
    float* out      = which ? g_ft  : g_fg;
    const float* w  = which ? wt    : wg;
    int b  = blockIdx.x;          // 0..3
    int pt = blockIdx.y;          // 0..15 (pixel tiles of 256)
    int tid = threadIdx.x;

    const float4* wsrc = (const float4*)(w + rq * 16 * CC);
    #pragma unroll
    for (int i = tid; i < 16 * CC / 4; i += 128) ((float4*)ws)[i] = wsrc[i];
    __syncthreads();

    int p0 = pt * 256 + tid;                  // second pixel at p0 + 128
    const float* inb = in + (size_t)b * CC * PL + p0;

    unsigned long long acc0[16], acc1[16];
    #pragma unroll
    for (int r = 0; r < 16; r++) { acc0[r] = 0ull; acc1[r] = 0ull; }

    for (int c = 0; c < CC; c += 4) {
        const float* ip = inb + (size_t)c * PL;
        float a0 = ip[0],      a1 = ip[PL],      a2 = ip[2*PL],      a3 = ip[3*PL];
        float b0 = ip[128],    b1 = ip[PL+128],  b2 = ip[2*PL+128],  b3 = ip[3*PL+128];
        unsigned long long ea0 = pk2(a0, a1), ea1 = pk2(a2, a3);
        unsigned long long eb0 = pk2(b0, b1), eb1 = pk2(b2, b3);
        #pragma unroll
        for (int r = 0; r < 16; r++) {
            const ulonglong2 wv = *(const ulonglong2*)(ws + r * CC + c);
            fma2(acc0[r], ea0, wv.x);
            fma2(acc0[r], ea1, wv.y);
            fma2(acc1[r], eb0, wv.x);
            fma2(acc1[r], eb1, wv.y);
        }
    }
    float* outp = out + ((size_t)b * RR + rq * 16) * PL + p0;
    #pragma unroll
    for (int r = 0; r < 16; r++) {
        outp[(size_t)r * PL]       = unpk_sum(acc0[r]);
        outp[(size_t)r * PL + 128] = unpk_sum(acc1[r]);
    }
}

// ---------- K3: 3x3 zero-padded box stats + guided-filter coefficients ----------
#define PITCH 66
__global__ __launch_bounds__(256) void k_guided(const float* __restrict__ epsPtr) {
    __shared__ float sg[PITCH*PITCH];
    __shared__ float st[PITCH*PITCH];
    int br = blockIdx.x;                       // b*RR + r, 256 blocks
    int tid = threadIdx.x;
    const float* gsrc = g_fg + (size_t)br * PL;
    const float* tsrc = g_ft + (size_t)br * PL;
    for (int i = tid; i < PITCH*PITCH; i += 256) { sg[i] = 0.0f; st[i] = 0.0f; }
    __syncthreads();
    for (int p = tid; p < PL; p += 256) {
        int i = p >> 6, j = p & 63;
        sg[(i+1)*PITCH + (j+1)] = gsrc[p];
        st[(i+1)*PITCH + (j+1)] = tsrc[p];
    }
    __syncthreads();
    float eps = *epsPtr;
    const float inv9 = 1.0f / 9.0f;
    for (int p = tid; p < PL; p += 256) {
        int i = p >> 6, j = p & 63;
        int c = (i+1)*PITCH + (j+1);
        float sgs = 0.f, sts = 0.f, sggs = 0.f, sgts = 0.f;
        #pragma unroll
        for (int di = -1; di <= 1; di++) {
            #pragma unroll
            for (int dj = -1; dj <= 1; dj++) {
                float g = sg[c + di*PITCH + dj];
                float t = st[c + di*PITCH + dj];
                sgs += g; sts += t; sggs += g*g; sgts += g*t;
            }
        }
        float mg  = sgs * inv9;
        float mt  = sts * inv9;
        float var = sggs * inv9 - mg * mg;
        float cov = sgts * inv9 - mg * mt;
        float a   = cov / (var + eps);
        float bb  = mt - a * mg;
        g_a[(size_t)br * PL + p] = a;
        g_b[(size_t)br * PL + p] = bb;
    }
}

// ---------- K4: expand: out[b,o,p] = sum_r w[o,r] * in[b,r,p]  (w: [C, R]) ----------
// Register-tiled: each thread computes 16 o-outputs for 2 pixels.
// blockIdx.z (32): bits[0:4) = o-group (16), bit4 = which tensor.
__global__ __launch_bounds__(128, 5) void k_expand(const float* __restrict__ wa,
                                                   const float* __restrict__ wb) {
    __shared__ float ws[16 * RR];
    int which = blockIdx.z >> 4;
    int og    = blockIdx.z & 15;
    const float* in = which ? g_b  : g_a;
    float* out      = which ? g_Bi : g_Ai;
    const float* w  = which ? wb   : wa;
    int b  = blockIdx.x;          // 0..3
    int pt = blockIdx.y;          // 0..15
    int tid = threadIdx.x;

    const float4* wsrc = (const float4*)(w + og * 16 * RR);
    #pragma unroll
    for (int i = tid; i < 16 * RR / 4; i += 128) ((float4*)ws)[i] = wsrc[i];
    __syncthreads();

    int p0 = pt * 256 + tid;
    const float* inb = in + (size_t)b * RR * PL + p0;

    unsigned long long acc0[16], acc1[16];
    #pragma unroll
    for (int o = 0; o < 16; o++) { acc0[o] = 0ull; acc1[o] = 0ull; }

    #pragma unroll 4
    for (int r = 0; r < RR; r += 4) {
        const float* ip = inb + (size_t)r * PL;
        float a0 = ip[0],      a1 = ip[PL],      a2 = ip[2*PL],      a3 = ip[3*PL];
        float b0 = ip[128],    b1 = ip[PL+128],  b2 = ip[2*PL+128],  b3 = ip[3*PL+128];
        unsigned long long ea0 = pk2(a0, a1), ea1 = pk2(a2, a3);
        unsigned long long eb0 = pk2(b0, b1), eb1 = pk2(b2, b3);
        #pragma unroll
        for (int o = 0; o < 16; o++) {
            const ulonglong2 wv = *(const ulonglong2*)(ws + o * RR + r);
            fma2(acc0[o], ea0, wv.x);
            fma2(acc0[o], ea1, wv.y);
            fma2(acc1[o], eb0, wv.x);
            fma2(acc1[o], eb1, wv.y);
        }
    }
    float* outp = out + ((size_t)b * CC + og * 16) * PL + p0;
    #pragma unroll
    for (int o = 0; o < 16; o++) {
        outp[(size_t)o * PL]       = unpk_sum(acc0[o]);
        outp[(size_t)o * PL + 128] = unpk_sum(acc1[o]);
    }
}

// ---------- K5: fused 4x bilinear upsample + output combine (SMEM-staged) ----------
__global__ __launch_bounds__(256) void k_final(const float* __restrict__ E,
                                               const float* __restrict__ D,
                                               float* __restrict__ out) {
    __shared__ float rawA[6][64], rawB[6][64];
    __shared__ float Ay[16][64], By[16][64];
    int bc = blockIdx.x;      // 0..1023
    int t  = blockIdx.y;      // 0..15 (y tiles of 16)
    int tid = threadIdx.x;
    int base = 4*t - 1;

    const float* Ab = g_Ai + (size_t)bc * PL;
    const float* Bb = g_Bi + (size_t)bc * PL;
    for (int i = tid; i < 6*64; i += 256) {
        int s = i >> 6, c = i & 63;
        int row = min(max(base + s, 0), 63);
        rawA[s][c] = Ab[row*64 + c];
        rawB[s][c] = Bb[row*64 + c];
    }
    __syncthreads();

    for (int i = tid; i < 16*64; i += 256) {
        int yl = i >> 6, c = i & 63;
        int y = t*16 + yl;
        float sy = fmaxf((y + 0.5f) * 0.25f - 0.5f, 0.0f);
        int y0 = (int)sy; if (y0 > 63) y0 = 63;
        int y1 = min(y0 + 1, 63);
        float wy = sy - (float)y0;
        int s0 = y0 - base, s1 = y1 - base;
        float a0 = rawA[s0][c], a1 = rawA[s1][c];
        float b0 = rawB[s0][c], b1 = rawB[s1][c];
        Ay[yl][c] = a0 + wy * (a1 - a0);
        By[yl][c] = b0 + wy * (b1 - b0);
    }
    __syncthreads();

    int yl = tid >> 4;        // 0..15
    int kq = tid & 15;        // 0..15
    int y  = t*16 + yl;
    size_t rowbase = ((size_t)bc * HH + y) * WW;

    #pragma unroll
    for (int g = 0; g < 4; g++) {
        int k = g*16 + kq;
        int cl = max(k - 1, 0);
        int cr = min(k + 1, 63);
        float al = Ay[yl][cl], am = Ay[yl][k], ar = Ay[yl][cr];
        float bl = By[yl][cl], bm = By[yl][k], br = By[yl][cr];

        float w0 = (k == 0) ? 0.0f : 0.625f;
        float w1 = (k == 0) ? 0.0f : 0.875f;
        float a0 = al + w0 * (am - al);
        float a1 = al + w1 * (am - al);
        float a2 = am + 0.125f * (ar - am);
        float a3 = am + 0.375f * (ar - am);
        float b0 = bl + w0 * (bm - bl);
        float b1 = bl + w1 * (bm - bl);
        float b2 = bm + 0.125f * (br - bm);
        float b3 = bm + 0.375f * (br - bm);

        size_t o4 = rowbase + 4*k;
        float4 e = *(const float4*)(E + o4);
        float4 d = *(const float4*)(D + o4);
        float4 o;
        o.x = d.x + a0 * e.x + b0;
        o.y = d.y + a1 * e.y + b1;
        o.z = d.z + a2 * e.z + b2;
        o.w = d.w + a3 * e.w + b3;
        *(float4*)(out + o4) = o;
    }
}

extern "C" void kernel_launch(void* const* d_in, const int* in_sizes, int n_in,
                              void* d_out, int out_size) {
    const float* F_enc = (const float*)d_in[0];
    const float* F_dec = (const float*)d_in[1];
    const float* w_rg  = (const float*)d_in[2];
    const float* w_rt  = (const float*)d_in[3];
    const float* w_ua  = (const float*)d_in[4];
    const float* w_ub  = (const float*)d_in[5];
    const float* eps   = (const float*)d_in[6];
    float* out = (float*)d_out;

    // K1: downsample both inputs 4x (coalesced float4 reads)
    k_down<<<(BB*CC*PL)/256, 256>>>(F_enc, F_dec);

    // K2: low-res projections to R channels (register-tiled, both tensors)
    k_proj<<<dim3(BB, 16, 8), 128>>>(w_rg, w_rt);

    // K3: box stats + a,b (branch-free padded tile)
    k_guided<<<BB*RR, 256>>>(eps);

    // K4: expand a,b to C channels at low res (register-tiled, both tensors)
    k_expand<<<dim3(BB, 16, 32), 128>>>(w_ua, w_ub);

    // K5: fused upsample + combine (SMEM-staged coefficients)
    k_final<<<dim3(BB*CC, HH/16), 256>>>(F_enc, F_dec, out);
}